// round 2
// baseline (speedup 1.0000x reference)
#include <cuda_runtime.h>

// InvLocalPatOrientConvolution — fused shell-decomposed implementation.
// out[b,E,o] = SUM_g w_l(g)*v_g^2 / (SUM_g w_l(g)*v_g + eps) + bias[E]
//   v_g = relu( SUM_s conv[s,E] * G[g,s] )
//   conv[s,E] = SUM_{c,r} wfull[lw_s, r, E, c] * z[c, lb_s, r]
//   z[c,lb,r] = SUM_{tap in shell r} x[b,c,o+tap] * sph[lb,tap]
// (lw_s, lb_s) = (0,0),(1,1),(1,2),(1,3),(2,1),(2,2),(2,3),(3,1),(3,2),(3,3)

#define OUT3 46656            // 36*36*36
#define EPSV 1e-16f

// ---------------- device scratch (static allocations only) ----------------
__device__ float  d_WT[4 * 10 * 16 * 16];   // [lw][r][c][E] = wfull[lw][r][E][c]
__device__ int    d_toff[125];              // tap offset within 8x8x8 tile (i*64+j*8+k)
__device__ float4 d_tsph[125];              // sph[0..3] at tap (taps sorted by shell)
__device__ int    d_tstart[11];             // shell start offsets

// ---------------- setup: tap tables + transposed dense weight ----------------
__global__ void setup_kernel(const float* __restrict__ weight,      // [4][9][16][16] (l, r-1, e=E, d=c)
                             const float* __restrict__ zeroweight,  // [16][16] (E, c)
                             const float* __restrict__ bf)          // [4][10][5][5][5]
{
    int tid = threadIdx.x;
    // dense wfull, transposed to [lw][r][c][E]
    for (int el = tid; el < 10240; el += blockDim.x) {
        int E   = el & 15;
        int c   = (el >> 4) & 15;
        int lwr = el >> 8;            // lw*10 + r
        int r   = lwr % 10;
        int lw  = lwr / 10;
        float v;
        if (r == 0) v = (lw == 0) ? zeroweight[E * 16 + c] : 0.0f;
        else        v = weight[((lw * 9 + (r - 1)) * 16 + E) * 16 + c];
        d_WT[el] = v;
    }
    if (tid == 0) {
        // derive shell index of each tap from bf[0][r][tap] (= C0 * mask_r)
        int rof[125];
        int cnt[10];
        for (int r = 0; r < 10; r++) cnt[r] = 0;
        for (int t = 0; t < 125; t++) {
            int rr = 0;
            for (int r = 0; r < 10; r++)
                if (fabsf(bf[r * 125 + t]) > 1e-3f) rr = r;
            rof[t] = rr;
            cnt[rr]++;
        }
        int st[11];
        st[0] = 0;
        for (int r = 0; r < 10; r++) st[r + 1] = st[r] + cnt[r];
        for (int r = 0; r < 11; r++) d_tstart[r] = st[r];
        int pos[10];
        for (int r = 0; r < 10; r++) pos[r] = st[r];
        for (int t = 0; t < 125; t++) {
            int rr = rof[t];
            int p = pos[rr]++;
            int i = t / 25, j = (t / 5) % 5, k = t % 5;
            d_toff[p] = i * 64 + j * 8 + k;
            d_tsph[p] = make_float4(bf[0 * 1250 + rr * 125 + t],
                                    bf[1 * 1250 + rr * 125 + t],
                                    bf[2 * 1250 + rr * 125 + t],
                                    bf[3 * 1250 + rr * 125 + t]);
        }
    }
}

// ---------------- shared-memory layout (float offsets) ----------------
// xs   [16][8][8][8]            : 0      .. 8192
// zsm  [c'(4)][lb(4)][r(10)][64]: 8192   .. 18432
// wts  [lw*10+r (40)][c'(4)][16]: 18432  .. 20992
// tsph float4[125]              : 20992  .. 21492
// toff int[125]                 : 21492  .. 21617
// Gs   [27][12]                 : 21620  .. 21944
// wlg  [27]                     : 21944  .. 21971
// bias [16]                     : 21972  .. 21988
#define SMEM_FLOATS 21992
#define SMEM_BYTES  (SMEM_FLOATS * 4)

__global__ void __launch_bounds__(256, 2)
main_kernel(const float* __restrict__ x,        // [2][16][40][40][40]
            const float* __restrict__ so3g,     // [27][10]
            const float* __restrict__ wi,       // [3]
            const float* __restrict__ bias,     // [16]
            float* __restrict__ out)            // [2][16][36][36][36]
{
    extern __shared__ float sm[];
    float*  xs   = sm;
    float*  zsm  = sm + 8192;
    float*  wts  = sm + 18432;
    float4* tsph = (float4*)(sm + 20992);
    int*    toff = (int*)(sm + 21492);
    float*  Gs   = sm + 21620;
    float*  wlg  = sm + 21944;
    float*  bis  = sm + 21972;
    __shared__ int tst[11];

    const int tid = threadIdx.x;
    const int b   = blockIdx.y;
    int tile = blockIdx.x;
    const int tzi = tile % 9; tile /= 9;
    const int tyi = tile % 9;
    const int txi = tile / 9;
    const int ox0 = txi * 4, oy0 = tyi * 4, oz0 = tzi * 4;

    // ---- load x tile: 16ch x 8x8x8, rows of 8 floats (2x float4) ----
    const float* xb = x + (size_t)b * 16 * 64000;
    for (int row = tid; row < 1024; row += 256) {
        int c  = row >> 6;
        int di = (row >> 3) & 7;
        int dj = row & 7;
        const float* src = xb + c * 64000 + (ox0 + di) * 1600 + (oy0 + dj) * 40 + oz0;
        float4 a0 = *(const float4*)(src);
        float4 a1 = *(const float4*)(src + 4);
        float* dst = xs + c * 512 + di * 64 + dj * 8;
        *(float4*)(dst)     = a0;
        *(float4*)(dst + 4) = a1;
    }
    // ---- tap tables, so3 grid, per-g weights, bias ----
    for (int t = tid; t < 125; t += 256) {
        tsph[t] = d_tsph[t];
        toff[t] = d_toff[t];
    }
    for (int i = tid; i < 270; i += 256)
        Gs[(i / 10) * 12 + (i % 10)] = so3g[i];
    if (tid < 27) wlg[tid] = wi[(tid / 3) % 3];
    if (tid < 16) bis[tid] = bias[tid];
    if (tid < 11) tst[tid] = d_tstart[tid];

    // z-phase identity: one (voxel, channel) pair per thread
    const int vz = tid & 63;
    const int cz = tid >> 6;
    const int vzbase = ((vz >> 4) & 3) * 64 + ((vz >> 2) & 3) * 8 + (vz & 3);
    // conv-phase identity: (voxel, 4-wide E group) per thread
    const int v  = tid >> 2;
    const int dg = tid & 3;
    const int Eg = dg << 2;

    float4 acc[10];
    #pragma unroll
    for (int s = 0; s < 10; s++) acc[s] = make_float4(0.f, 0.f, 0.f, 0.f);

    #pragma unroll 1
    for (int chunk = 0; chunk < 4; chunk++) {
        __syncthreads();   // prev conv done reading zsm/wts; first iter: loads done

        // load this chunk's weight slice: WT[lw][r][c in chunk][E]
        for (int el = tid; el < 2560; el += 256) {
            int lwr = el >> 6;
            int ce  = el & 63;
            wts[el] = d_WT[lwr * 256 + chunk * 64 + ce];
        }

        // ---- z phase: shells of taps, 4 harmonics at once ----
        {
            const float* xc = xs + (4 * chunk + cz) * 512 + vzbase;
            float* zr = zsm + cz * 2560 + vz;
            for (int r = 0; r < 10; r++) {
                float z0 = 0.f, z1 = 0.f, z2 = 0.f, z3 = 0.f;
                const int t1 = tst[r + 1];
                for (int t = tst[r]; t < t1; t++) {
                    float  xv = xc[toff[t]];
                    float4 s4 = tsph[t];
                    z0 = fmaf(xv, s4.x, z0);
                    z1 = fmaf(xv, s4.y, z1);
                    z2 = fmaf(xv, s4.z, z2);
                    z3 = fmaf(xv, s4.w, z3);
                }
                zr[        r * 64] = z0;
                zr[ 640 +  r * 64] = z1;
                zr[1280 +  r * 64] = z2;
                zr[1920 +  r * 64] = z3;
            }
        }
        __syncthreads();

        // ---- mix phase: acc[s] += WT[lw_s][r][c][E..E+3] * z[c][lb_s][r] ----
        #pragma unroll
        for (int cc = 0; cc < 4; cc++) {
            const float* zp = zsm + cc * 2560 + v;
            const float* wp = wts + cc * 16 + Eg;
            #pragma unroll
            for (int r = 0; r < 10; r++) {
                float z0 = zp[        r * 64];
                float z1 = zp[ 640 +  r * 64];
                float z2 = zp[1280 +  r * 64];
                float z3 = zp[1920 +  r * 64];
                float4 w0 = *(const float4*)(wp +         r * 64);
                float4 w1 = *(const float4*)(wp +  640 +  r * 64);
                float4 w2 = *(const float4*)(wp + 1280 +  r * 64);
                float4 w3 = *(const float4*)(wp + 1920 +  r * 64);
                // s=0: (lw0, lb0)
                acc[0].x = fmaf(w0.x, z0, acc[0].x);
                acc[0].y = fmaf(w0.y, z0, acc[0].y);
                acc[0].z = fmaf(w0.z, z0, acc[0].z);
                acc[0].w = fmaf(w0.w, z0, acc[0].w);
                // s=1..3: lw1 with lb1..3
                acc[1].x = fmaf(w1.x, z1, acc[1].x);
                acc[1].y = fmaf(w1.y, z1, acc[1].y);
                acc[1].z = fmaf(w1.z, z1, acc[1].z);
                acc[1].w = fmaf(w1.w, z1, acc[1].w);
                acc[2].x = fmaf(w1.x, z2, acc[2].x);
                acc[2].y = fmaf(w1.y, z2, acc[2].y);
                acc[2].z = fmaf(w1.z, z2, acc[2].z);
                acc[2].w = fmaf(w1.w, z2, acc[2].w);
                acc[3].x = fmaf(w1.x, z3, acc[3].x);
                acc[3].y = fmaf(w1.y, z3, acc[3].y);
                acc[3].z = fmaf(w1.z, z3, acc[3].z);
                acc[3].w = fmaf(w1.w, z3, acc[3].w);
                // s=4..6: lw2 with lb1..3
                acc[4].x = fmaf(w2.x, z1, acc[4].x);
                acc[4].y = fmaf(w2.y, z1, acc[4].y);
                acc[4].z = fmaf(w2.z, z1, acc[4].z);
                acc[4].w = fmaf(w2.w, z1, acc[4].w);
                acc[5].x = fmaf(w2.x, z2, acc[5].x);
                acc[5].y = fmaf(w2.y, z2, acc[5].y);
                acc[5].z = fmaf(w2.z, z2, acc[5].z);
                acc[5].w = fmaf(w2.w, z2, acc[5].w);
                acc[6].x = fmaf(w2.x, z3, acc[6].x);
                acc[6].y = fmaf(w2.y, z3, acc[6].y);
                acc[6].z = fmaf(w2.z, z3, acc[6].z);
                acc[6].w = fmaf(w2.w, z3, acc[6].w);
                // s=7..9: lw3 with lb1..3
                acc[7].x = fmaf(w3.x, z1, acc[7].x);
                acc[7].y = fmaf(w3.y, z1, acc[7].y);
                acc[7].z = fmaf(w3.z, z1, acc[7].z);
                acc[7].w = fmaf(w3.w, z1, acc[7].w);
                acc[8].x = fmaf(w3.x, z2, acc[8].x);
                acc[8].y = fmaf(w3.y, z2, acc[8].y);
                acc[8].z = fmaf(w3.z, z2, acc[8].z);
                acc[8].w = fmaf(w3.w, z2, acc[8].w);
                acc[9].x = fmaf(w3.x, z3, acc[9].x);
                acc[9].y = fmaf(w3.y, z3, acc[9].y);
                acc[9].z = fmaf(w3.z, z3, acc[9].z);
                acc[9].w = fmaf(w3.w, z3, acc[9].w);
            }
        }
    }

    // ---- epilogue: so3 projection + relu + fused num/denom reduction ----
    float4 num = make_float4(0.f, 0.f, 0.f, 0.f);
    float4 den = make_float4(0.f, 0.f, 0.f, 0.f);
    #pragma unroll
    for (int g = 0; g < 27; g++) {
        const float* gr = Gs + g * 12;
        float4 t = make_float4(0.f, 0.f, 0.f, 0.f);
        #pragma unroll
        for (int s = 0; s < 10; s++) {
            float gv = gr[s];
            t.x = fmaf(acc[s].x, gv, t.x);
            t.y = fmaf(acc[s].y, gv, t.y);
            t.z = fmaf(acc[s].z, gv, t.z);
            t.w = fmaf(acc[s].w, gv, t.w);
        }
        t.x = fmaxf(t.x, 0.f);
        t.y = fmaxf(t.y, 0.f);
        t.z = fmaxf(t.z, 0.f);
        t.w = fmaxf(t.w, 0.f);
        float wl = wlg[g];
        den.x = fmaf(t.x, wl, den.x);
        den.y = fmaf(t.y, wl, den.y);
        den.z = fmaf(t.z, wl, den.z);
        den.w = fmaf(t.w, wl, den.w);
        num.x = fmaf(t.x * t.x, wl, num.x);
        num.y = fmaf(t.y * t.y, wl, num.y);
        num.z = fmaf(t.z * t.z, wl, num.z);
        num.w = fmaf(t.w * t.w, wl, num.w);
    }

    const int vi = v >> 4, vj = (v >> 2) & 3, vk = v & 3;
    const int ox = ox0 + vi, oy = oy0 + vj, oz = oz0 + vk;
    float4 bb = *(const float4*)(bis + Eg);
    float* op = out + ((size_t)b * 16 + Eg) * OUT3 + (ox * 36 + oy) * 36 + oz;
    op[0 * OUT3] = num.x / (den.x + EPSV) + bb.x;
    op[1 * OUT3] = num.y / (den.y + EPSV) + bb.y;
    op[2 * OUT3] = num.z / (den.z + EPSV) + bb.z;
    op[3 * OUT3] = num.w / (den.w + EPSV) + bb.w;
}

// ---------------- launch ----------------
extern "C" void kernel_launch(void* const* d_in, const int* in_sizes, int n_in,
                              void* d_out, int out_size)
{
    (void)in_sizes; (void)n_in; (void)out_size;
    const float* x    = (const float*)d_in[0];
    const float* wt   = (const float*)d_in[1];
    const float* zw   = (const float*)d_in[2];
    const float* bias = (const float*)d_in[3];
    const float* so3  = (const float*)d_in[4];
    const float* wi   = (const float*)d_in[5];
    const float* bf   = (const float*)d_in[6];
    // d_in[7] (wig_w) / d_in[8] (wig_b): fixed by ORDER=2 construction, baked in.

    cudaFuncSetAttribute(main_kernel,
                         cudaFuncAttributeMaxDynamicSharedMemorySize, SMEM_BYTES);

    setup_kernel<<<1, 256>>>(wt, zw, bf);
    main_kernel<<<dim3(729, 2), 256, SMEM_BYTES>>>(x, so3, wi, bias, (float*)d_out);
}